// round 9
// baseline (speedup 1.0000x reference)
#include <cuda_runtime.h>

typedef unsigned long long u64;

#define B_SZ   2048
#define T_LEN  256
#define E_DIM  50
#define H_DIM  50
#define G_DIM  200   // 4H
#define KP     52    // padded row (13 * float4 = 26 f32x2)
#define BPC    7     // batches per CTA
#define BPR    8     // padded rows (batch 7 = zeros, discarded)
#define NT     512   // 16 warps: 400 gate, 100 dense, 12 spare
#define GRID   293   // ceil(2048/7)
#define ITEMS  (BPC * 50)   // 350 update/emb items

__device__ __forceinline__ u64 ffma2(u64 a, u64 b, u64 c) {
    u64 d; asm("fma.rn.f32x2 %0, %1, %2, %3;" : "=l"(d) : "l"(a), "l"(b), "l"(c));
    return d;
}
__device__ __forceinline__ u64 pack2(float lo, float hi) {
    u64 d; asm("mov.b64 %0, {%1, %2};" : "=l"(d) : "f"(lo), "f"(hi)); return d;
}
__device__ __forceinline__ float sum2(u64 v) {
    float lo, hi; asm("mov.b64 {%0, %1}, %2;" : "=f"(lo), "=f"(hi) : "l"(v));
    return lo + hi;
}
__device__ __forceinline__ float tanhapx(float x) {
    float y; asm("tanh.approx.f32 %0, %1;" : "=f"(y) : "f"(x)); return y;
}
__device__ __forceinline__ float sigapx(float x) {
    return fmaf(tanhapx(0.5f * x), 0.5f, 0.5f);
}

// ---- gate weights: 50 scalars as 25 packed u64 (strided global load) ----
#define LDWP(m) const u64 wp##m = act ? \
    pack2(wb[(2*(m)) * G_DIM], wb[(2*(m)+1) * G_DIM]) : 0ull;

// One ulonglong2 (4 floats) of both rows in a block-pair vs 2 weight pairs
#define GPP(i, m0, m1) { ulonglong2 qa = svA[i], qb = svB[i]; \
    aA0 = ffma2(qa.x, wp##m0, aA0); aA1 = ffma2(qa.y, wp##m1, aA1); \
    aB0 = ffma2(qb.x, wp##m0, aB0); aB1 = ffma2(qb.y, wp##m1, aB1); }

#define GATE_PAIR_BODY \
    GPP(0,0,1)   GPP(1,2,3)   GPP(2,4,5)   GPP(3,6,7)   GPP(4,8,9) \
    GPP(5,10,11) GPP(6,12,13) GPP(7,14,15) GPP(8,16,17) GPP(9,18,19) \
    GPP(10,20,21) GPP(11,22,23) GPP(12,24,25)

// ---- dense weights: W1 column dj, 50 scalars as 25 packed u64 ----
#define LDWD(m) const u64 wd##m = dact ? \
    pack2(W1[(2*(m)) * E_DIM + dj], W1[(2*(m)+1) * E_DIM + dj]) : 0ull;

#define DPP(i, m0, m1) { ulonglong2 q = sv[i]; \
    a0 = ffma2(q.x, wd##m0, a0); a1 = ffma2(q.y, wd##m1, a1); }

#define DROW(SRC, DST) { \
    const ulonglong2* sv = (const ulonglong2*)(SRC); \
    u64 a0 = pack2(b1j, 0.f), a1 = 0ull; \
    DPP(0,0,1)   DPP(1,2,3)   DPP(2,4,5)   DPP(3,6,7)   DPP(4,8,9) \
    DPP(5,10,11) DPP(6,12,13) DPP(7,14,15) DPP(8,16,17) DPP(9,18,19) \
    DPP(10,20,21) DPP(11,22,23) DPP(12,24,25) \
    (DST) = fmaxf(sum2(a0) + sum2(a1), 0.f); }

__global__ void __launch_bounds__(NT, 2)
lstm_fused_all(const int* __restrict__ inp, const float* __restrict__ emb,
               const float* __restrict__ Wk, const float* __restrict__ Uk,
               const float* __restrict__ bias,
               const float* __restrict__ W1, const float* __restrict__ b1,
               const float* __restrict__ W2, const float* __restrict__ b2,
               float* __restrict__ out)
{
    __shared__ __align__(16) float xsh[2][BPR][KP];      // embedded inputs
    __shared__ __align__(16) float hsh[BPR][KP];         // hidden state
    __shared__ __align__(16) float zpart[2][BPR][G_DIM]; // gate partials
    __shared__ __align__(16) float d1b[2][BPC][KP];      // d1 (parity by step)
    __shared__ __align__(16) float d2b[2][BPC][KP];      // d2 (parity by step)
    __shared__ __align__(16) float w2s[KP];

    const int tid = threadIdx.x;
    const int b0  = blockIdx.x * BPC;

    // ---- gate threads: tid < 400; role 0 = x@Wk, role 1 = h@Uk ----
    const bool act  = (tid < 2 * G_DIM);
    const int  role = (tid >= G_DIM) ? 1 : 0;
    const int  g    = act ? (tid % G_DIM) : 0;
    const float* wb = (role ? Uk : Wk) + g;
    LDWP(0)  LDWP(1)  LDWP(2)  LDWP(3)  LDWP(4)  LDWP(5)  LDWP(6)
    LDWP(7)  LDWP(8)  LDWP(9)  LDWP(10) LDWP(11) LDWP(12) LDWP(13)
    LDWP(14) LDWP(15) LDWP(16) LDWP(17) LDWP(18) LDWP(19) LDWP(20)
    LDWP(21) LDWP(22) LDWP(23) LDWP(24)
    const u64 wp25 = 0ull;   // multiplies the zero pad (floats 50,51)
    const float bg = (act && role == 0) ? bias[g] : 0.f;

    // ---- dense threads: tid in [400, 500); dh 0 = d1 pass + out, 1 = d2 ----
    const bool dact = (tid >= 400) && (tid < 500);
    const int  dj   = dact ? ((tid - 400) % E_DIM) : 0;
    const int  dh   = dact ? ((tid - 400) / E_DIM) : 0;
    LDWD(0)  LDWD(1)  LDWD(2)  LDWD(3)  LDWD(4)  LDWD(5)  LDWD(6)
    LDWD(7)  LDWD(8)  LDWD(9)  LDWD(10) LDWD(11) LDWD(12) LDWD(13)
    LDWD(14) LDWD(15) LDWD(16) LDWD(17) LDWD(18) LDWD(19) LDWD(20)
    LDWD(21) LDWD(22) LDWD(23) LDWD(24)
    const u64 wd25 = 0ull;   // multiplies the zero pad (floats 50,51)
    const float b1j = dact ? b1[dj] : 0.f;
    // out-writer threads: dh 0, dj < BPC
    const bool oact = dact && (dh == 0) && (dj < BPC) && (b0 + dj < B_SZ);
    const float b2v = oact ? b2[0] : 0.f;

    // Zero padded shared rows (pads + row 7 stay zero forever)
    for (int i = tid; i < BPR * KP; i += NT) {
        (&hsh[0][0])[i]    = 0.f;
        (&xsh[0][0][0])[i] = 0.f;
        (&xsh[1][0][0])[i] = 0.f;
    }
    for (int i = tid; i < BPC * KP; i += NT) {
        (&d1b[0][0][0])[i] = 0.f;
        (&d1b[1][0][0])[i] = 0.f;
        (&d2b[0][0][0])[i] = 0.f;
        (&d2b[1][0][0])[i] = 0.f;
    }
    for (int i = tid; i < KP; i += NT) w2s[i] = (i < E_DIM) ? W2[i] : 0.f;

    // ---- update / prefetch: one item per thread (350 items) ----
    const bool v0  = (tid < ITEMS);
    const int  bl0 = v0 ? (tid / 50) : 0;
    const int  q0  = v0 ? (tid % 50) : 0;
    const bool s0  = v0 && (b0 + bl0 < B_SZ);
    const int* ir0 = inp + (size_t)(s0 ? (b0 + bl0) : 0) * T_LEN;
    float cst0 = 0.f, pre0 = 0.f;

    __syncthreads();
    if (v0) xsh[0][bl0][q0] = s0 ? emb[(size_t)ir0[0] * E_DIM + q0] : 0.f;
    __syncthreads();

    // Pipelined loop: iter t runs gates(t) || d1(t-1) || d2(t-2) || out(t-3)
    for (int t = 0; t < T_LEN + 3; t++) {
        const int  cur = t & 1, nxt = cur ^ 1;
        const bool doStep = (t < T_LEN);

        pre0 = 0.f;
        if (s0 && t + 1 < T_LEN)
            pre0 = emb[(size_t)ir0[t + 1] * E_DIM + q0];

        if (act) {
            // ---- gates(t): 4 block-pairs over padded 8 rows ----
            if (doStep) {
                #pragma unroll 1
                for (int blp = 0; blp < BPR; blp += 2) {
                    const ulonglong2* svA = (const ulonglong2*)
                        (role ? hsh[blp]     : xsh[cur][blp]);
                    const ulonglong2* svB = (const ulonglong2*)
                        (role ? hsh[blp + 1] : xsh[cur][blp + 1]);
                    u64 aA0 = pack2(bg, 0.f), aA1 = 0ull;
                    u64 aB0 = pack2(bg, 0.f), aB1 = 0ull;
                    GATE_PAIR_BODY
                    zpart[role][blp][g]     = sum2(aA0) + sum2(aA1);
                    zpart[role][blp + 1][g] = sum2(aB0) + sum2(aB1);
                }
            }
        } else if (dact) {
            if (dh == 0) {
                // ---- out(t-3): sigmoid(d2(t-3) . W2 + b2) ----
                if (t >= 3 && oact) {
                    const float4* sv = (const float4*)d2b[(t - 3) & 1][dj];
                    const float4* wv = (const float4*)w2s;
                    float r0 = b2v, r1 = 0.f, r2 = 0.f, r3 = 0.f;
                    #pragma unroll
                    for (int p = 0; p < 13; p++) {
                        float4 x = sv[p], y = wv[p];
                        r0 = fmaf(x.x, y.x, r0); r1 = fmaf(x.y, y.y, r1);
                        r2 = fmaf(x.z, y.z, r2); r3 = fmaf(x.w, y.w, r3);
                    }
                    out[(size_t)(b0 + dj) * T_LEN + (t - 3)] =
                        sigapx((r0 + r1) + (r2 + r3));
                }
                // ---- d1(t-1) = relu(h(t-1) @ W1 + b1) ----
                if (t >= 1 && t <= T_LEN) {
                    const int pw = (t - 1) & 1;
                    #pragma unroll 1
                    for (int bl = 0; bl < BPC; bl++)
                        DROW(hsh[bl], d1b[pw][bl][dj]);
                }
            } else {
                // ---- d2(t-2) = relu(d1(t-2) @ W1 + b1) ----
                if (t >= 2 && t <= T_LEN + 1) {
                    const int pw = (t - 2) & 1;
                    #pragma unroll 1
                    for (int bl = 0; bl < BPC; bl++)
                        DROW(d1b[pw][bl], d2b[pw][bl][dj]);
                }
            }
        }
        __syncthreads();

        // ---- state update (Keras order i,f,c,o) + commit x(t+1) ----
        if (doStep && v0) {
            float zi = zpart[0][bl0][q0]       + zpart[1][bl0][q0];
            float zf = zpart[0][bl0][q0 +  50] + zpart[1][bl0][q0 +  50];
            float zg = zpart[0][bl0][q0 + 100] + zpart[1][bl0][q0 + 100];
            float zo = zpart[0][bl0][q0 + 150] + zpart[1][bl0][q0 + 150];
            float ig = sigapx(zi), fg = sigapx(zf);
            float gg = tanhapx(zg), og = sigapx(zo);
            cst0 = fg * cst0 + ig * gg;
            hsh[bl0][q0] = og * tanhapx(cst0);
            xsh[nxt][bl0][q0] = pre0;
        }
        __syncthreads();
    }
}

// ---------------------------------------------------------------------------
extern "C" void kernel_launch(void* const* d_in, const int* in_sizes, int n_in,
                              void* d_out, int out_size)
{
    const int*   inp = (const int*)  d_in[0];
    const float* emb = (const float*)d_in[1];
    const float* Wk  = (const float*)d_in[2];
    const float* Uk  = (const float*)d_in[3];
    const float* b   = (const float*)d_in[4];
    const float* W1  = (const float*)d_in[5];
    const float* b1  = (const float*)d_in[6];
    const float* W2  = (const float*)d_in[7];
    const float* b2  = (const float*)d_in[8];
    float* out = (float*)d_out;

    lstm_fused_all<<<GRID, NT>>>(inp, emb, Wk, Uk, b, W1, b1, W2, b2, out);
}

// round 10
// speedup vs baseline: 2.9034x; 2.9034x over previous
#include <cuda_runtime.h>

typedef unsigned long long u64;

#define B_SZ   2048
#define T_LEN  256
#define E_DIM  50
#define H_DIM  50
#define G_DIM  200   // 4H
#define KP     52    // padded row (13 * float4 = 26 f32x2)
#define BPC    14    // batches per CTA
#define NT     416   // 13 warps; 400 gate threads
#define GRID   147   // ceil(2048/14)
#define ITEMS  (BPC * 50)   // 700 items: q-major (q = it/BPC, bl = it%BPC)

__device__ __forceinline__ u64 ffma2(u64 a, u64 b, u64 c) {
    u64 d; asm("fma.rn.f32x2 %0, %1, %2, %3;" : "=l"(d) : "l"(a), "l"(b), "l"(c));
    return d;
}
__device__ __forceinline__ u64 pack2(float lo, float hi) {
    u64 d; asm("mov.b64 %0, {%1, %2};" : "=l"(d) : "f"(lo), "f"(hi)); return d;
}
__device__ __forceinline__ float sum2(u64 v) {
    float lo, hi; asm("mov.b64 {%0, %1}, %2;" : "=f"(lo), "=f"(hi) : "l"(v));
    return lo + hi;
}
__device__ __forceinline__ float tanhapx(float x) {
    float y; asm("tanh.approx.f32 %0, %1;" : "=f"(y) : "f"(x)); return y;
}
__device__ __forceinline__ float sigapx(float x) {
    return fmaf(tanhapx(0.5f * x), 0.5f, 0.5f);
}

// f32x2 dot of two padded-52 smem rows + bias (pads are zero)
__device__ __forceinline__ float dot52x2(const float* __restrict__ a,
                                         const float* __restrict__ b,
                                         float bias) {
    const ulonglong2* av = (const ulonglong2*)a;
    const ulonglong2* bv = (const ulonglong2*)b;
    u64 s0 = pack2(bias, 0.f), s1 = 0ull;
    #pragma unroll
    for (int p = 0; p < 13; p++) {
        ulonglong2 x = av[p], y = bv[p];
        s0 = ffma2(x.x, y.x, s0);
        s1 = ffma2(x.y, y.y, s1);
    }
    return sum2(s0) + sum2(s1);
}

// ---- gate weights: 50 scalars as 25 packed u64 (strided global load) ----
#define LDWP(m) const u64 wp##m = act ? \
    pack2(wb[(2*(m)) * G_DIM], wb[(2*(m)+1) * G_DIM]) : 0ull;

// One ulonglong2 (4 floats) of both rows in a block-pair vs 2 weight pairs
#define GPP(i, m0, m1) { ulonglong2 qa = svA[i], qb = svB[i]; \
    aA0 = ffma2(qa.x, wp##m0, aA0); aA1 = ffma2(qa.y, wp##m1, aA1); \
    aB0 = ffma2(qb.x, wp##m0, aB0); aB1 = ffma2(qb.y, wp##m1, aB1); }

#define GATE_PAIR_BODY \
    GPP(0,0,1)   GPP(1,2,3)   GPP(2,4,5)   GPP(3,6,7)   GPP(4,8,9) \
    GPP(5,10,11) GPP(6,12,13) GPP(7,14,15) GPP(8,16,17) GPP(9,18,19) \
    GPP(10,20,21) GPP(11,22,23) GPP(12,24,25)

// ---- item slots (q-major: lanes within a warp mostly share q) ----
#define ITEM_SETUP(r) \
    const int  u##r  = tid + (r) * NT; \
    const bool v##r  = (u##r < ITEMS); \
    const int  q##r  = v##r ? (u##r / BPC) : 0; \
    const int  bl##r = v##r ? (u##r % BPC) : 0; \
    const bool s##r  = v##r && (b0 + bl##r < B_SZ); \
    const int* ir##r = inp + (size_t)(s##r ? (b0 + bl##r) : 0) * T_LEN; \
    float cst##r = 0.f; float pre##r = 0.f;

#define PRELOAD(r) if (v##r) \
    xsh[0][bl##r][q##r] = s##r ? emb[(size_t)ir##r[0] * E_DIM + q##r] : 0.f;

#define PFETCH(r) { pre##r = 0.f; \
    if (s##r && t + 1 < T_LEN) pre##r = emb[(size_t)ir##r[t + 1] * E_DIM + q##r]; }

#define UPDATE(r) if (v##r) { \
    float zi = zpart[0][bl##r][q##r]       + zpart[1][bl##r][q##r]; \
    float zf = zpart[0][bl##r][q##r +  50] + zpart[1][bl##r][q##r +  50]; \
    float zg = zpart[0][bl##r][q##r + 100] + zpart[1][bl##r][q##r + 100]; \
    float zo = zpart[0][bl##r][q##r + 150] + zpart[1][bl##r][q##r + 150]; \
    float ig = sigapx(zi), fg = sigapx(zf); \
    float gg = tanhapx(zg), og = sigapx(zo); \
    cst##r = fg * cst##r + ig * gg; \
    hsh[bl##r][q##r] = og * tanhapx(cst##r); \
    xsh[nxt][bl##r][q##r] = pre##r; }

#define DENSE1(r) if (v##r) \
    d1sh[bl##r][q##r] = fmaxf(dot52x2(hsh[bl##r], w1ts[q##r], b1s[q##r]), 0.f);
#define DENSE2(r) if (v##r) \
    d2sh[bl##r][q##r] = fmaxf(dot52x2(d1sh[bl##r], w1ts[q##r], b1s[q##r]), 0.f);

__global__ void __launch_bounds__(NT, 1)
lstm_fused_all(const int* __restrict__ inp, const float* __restrict__ emb,
               const float* __restrict__ Wk, const float* __restrict__ Uk,
               const float* __restrict__ bias,
               const float* __restrict__ W1, const float* __restrict__ b1,
               const float* __restrict__ W2, const float* __restrict__ b2,
               float* __restrict__ out)
{
    __shared__ __align__(16) float xsh[2][BPC][KP];      // embedded inputs
    __shared__ __align__(16) float hsh[BPC][KP];         // hidden state
    __shared__ __align__(16) float zpart[2][BPC][G_DIM]; // gate partials
    __shared__ __align__(16) float w1ts[E_DIM][KP];      // w1ts[j][k] = W1[k][j]
    __shared__ __align__(16) float d1sh[BPC][KP];
    __shared__ __align__(16) float d2sh[BPC][KP];
    __shared__ __align__(16) float w2s[KP];
    __shared__ float b1s[E_DIM];
    __shared__ float b2sh;

    const int tid = threadIdx.x;
    const int b0  = blockIdx.x * BPC;

    // ---- gate threads: tid < 400; role 0 = x@Wk, role 1 = h@Uk ----
    const bool act  = (tid < 2 * G_DIM);
    const int  role = (tid >= G_DIM) ? 1 : 0;
    const int  g    = act ? (tid % G_DIM) : 0;
    const float* wb = (role ? Uk : Wk) + g;
    LDWP(0)  LDWP(1)  LDWP(2)  LDWP(3)  LDWP(4)  LDWP(5)  LDWP(6)
    LDWP(7)  LDWP(8)  LDWP(9)  LDWP(10) LDWP(11) LDWP(12) LDWP(13)
    LDWP(14) LDWP(15) LDWP(16) LDWP(17) LDWP(18) LDWP(19) LDWP(20)
    LDWP(21) LDWP(22) LDWP(23) LDWP(24)
    const u64 wp25 = 0ull;   // multiplies the zero pad (floats 50,51)
    const float bg = (act && role == 0) ? bias[g] : 0.f;

    // Zero padded shared rows (pads stay zero forever)
    for (int i = tid; i < BPC * KP; i += NT) {
        (&hsh[0][0])[i]    = 0.f;
        (&xsh[0][0][0])[i] = 0.f;
        (&xsh[1][0][0])[i] = 0.f;
        (&d1sh[0][0])[i]   = 0.f;
        (&d2sh[0][0])[i]   = 0.f;
    }
    // Dense weights into shared (transposed, padded)
    for (int i = tid; i < E_DIM * KP; i += NT) {
        int j = i / KP, k = i % KP;
        w1ts[j][k] = (k < H_DIM) ? W1[k * E_DIM + j] : 0.f;
    }
    for (int i = tid; i < KP; i += NT) w2s[i] = (i < E_DIM) ? W2[i] : 0.f;
    if (tid < E_DIM) b1s[tid] = b1[tid];
    if (tid == 0)    b2sh = b2[0];

    ITEM_SETUP(0) ITEM_SETUP(1)
    __syncthreads();
    PRELOAD(0) PRELOAD(1)
    __syncthreads();

    for (int t = 0; t < T_LEN; t++) {
        const int cur = t & 1, nxt = cur ^ 1;

        // Prefetch embeddings for t+1 (LDG latency hidden behind gate math)
        PFETCH(0) PFETCH(1)

        // ---- gates(t): block pairs, f32x2, 4 independent accumulator chains
        if (act) {
            #pragma unroll 1
            for (int blp = 0; blp < BPC; blp += 2) {
                const ulonglong2* svA = (const ulonglong2*)
                    (role ? hsh[blp]     : xsh[cur][blp]);
                const ulonglong2* svB = (const ulonglong2*)
                    (role ? hsh[blp + 1] : xsh[cur][blp + 1]);
                u64 aA0 = pack2(bg, 0.f), aA1 = 0ull;
                u64 aB0 = pack2(bg, 0.f), aB1 = 0ull;
                GATE_PAIR_BODY
                zpart[role][blp][g]     = sum2(aA0) + sum2(aA1);
                zpart[role][blp + 1][g] = sum2(aB0) + sum2(aB1);
            }
        }
        __syncthreads();

        // ---- state update (Keras order i,f,c,o) + commit x(t+1) ----
        UPDATE(0) UPDATE(1)
        __syncthreads();

        // ---- d1 = relu(h @ W1 + b1) ----
        DENSE1(0) DENSE1(1)
        __syncthreads();

        // ---- d2 = relu(d1 @ W1 + b1) ----
        DENSE2(0) DENSE2(1)
        __syncthreads();

        // ---- out: sigmoid(d2 . W2 + b2); overlaps next step's gate phase ----
        if (tid < BPC && b0 + tid < B_SZ) {
            float acc = dot52x2(d2sh[tid], w2s, b2sh);
            out[(size_t)(b0 + tid) * T_LEN + t] = sigapx(acc);
        }
    }
}

// ---------------------------------------------------------------------------
extern "C" void kernel_launch(void* const* d_in, const int* in_sizes, int n_in,
                              void* d_out, int out_size)
{
    const int*   inp = (const int*)  d_in[0];
    const float* emb = (const float*)d_in[1];
    const float* Wk  = (const float*)d_in[2];
    const float* Uk  = (const float*)d_in[3];
    const float* b   = (const float*)d_in[4];
    const float* W1  = (const float*)d_in[5];
    const float* b1  = (const float*)d_in[6];
    const float* W2  = (const float*)d_in[7];
    const float* b2  = (const float*)d_in[8];
    float* out = (float*)d_out;

    lstm_fused_all<<<GRID, NT>>>(inp, emb, Wk, Uk, b, W1, b1, W2, b2, out);
}